// round 1
// baseline (speedup 1.0000x reference)
#include <cuda_runtime.h>
#include <cuda_bf16.h>

#define GD 128
#define GRID_ELEMS (GD * GD * GD)

// 8 MB scratch diff-grid (pred splat adds +w, gt splat adds -w).
__device__ float g_grid[GRID_ELEMS];

// ---------------------------------------------------------------------------
// Kernel 1: zero the diff grid (vectorized) and the scalar output.
// ---------------------------------------------------------------------------
__global__ void zero_kernel(float* __restrict__ out) {
    int i = blockIdx.x * blockDim.x + threadIdx.x;
    float4* p = reinterpret_cast<float4*>(g_grid);
    const int n4 = GRID_ELEMS / 4;
    if (i < n4) p[i] = make_float4(0.f, 0.f, 0.f, 0.f);
    if (i == 0) *out = 0.f;
}

// ---------------------------------------------------------------------------
// Kernel 2: trilinear scatter. Thread i < N handles pred point i with +1,
// thread i >= N handles gt point (i-N) with -1. 8 RED.ADD per thread.
// ---------------------------------------------------------------------------
__global__ void splat_kernel(const float* __restrict__ pred,
                             const float* __restrict__ gt,
                             const float* __restrict__ coords,
                             int N) {
    int i = blockIdx.x * blockDim.x + threadIdx.x;
    if (i >= 2 * N) return;

    const bool is_pred = (i < N);
    const int p = is_pred ? i : (i - N);
    const float* __restrict__ reg = is_pred ? pred : gt;
    const float sign = is_pred ? 1.0f : -1.0f;

    const float cx = coords[3 * p + 0] + reg[3 * p + 0];
    const float cy = coords[3 * p + 1] + reg[3 * p + 1];
    const float cz = coords[3 * p + 2] + reg[3 * p + 2];

    // pixel = ((c + 1) * 128 - 1) * 0.5 = 64*c + 63.5
    const float x = fmaf(cx, 64.0f, 63.5f);
    const float y = fmaf(cy, 64.0f, 63.5f);
    const float z = fmaf(cz, 64.0f, 63.5f);

    const float x0f = floorf(x), y0f = floorf(y), z0f = floorf(z);
    const float fx = x - x0f, fy = y - y0f, fz = z - z0f;
    const int x0 = (int)x0f, y0 = (int)y0f, z0 = (int)z0f;

    const float wx0 = 1.0f - fx, wx1 = fx;
    const float wy0 = 1.0f - fy, wy1 = fy;
    const float wz0 = 1.0f - fz, wz1 = fz;

    #pragma unroll
    for (int dz = 0; dz < 2; ++dz) {
        const int zi = z0 + dz;
        if ((unsigned)zi >= (unsigned)GD) continue;
        const float wz = (dz ? wz1 : wz0) * sign;
        #pragma unroll
        for (int dy = 0; dy < 2; ++dy) {
            const int yi = y0 + dy;
            if ((unsigned)yi >= (unsigned)GD) continue;
            const float wyz = (dy ? wy1 : wy0) * wz;
            const int base = (zi * GD + yi) * GD;
            #pragma unroll
            for (int dx = 0; dx < 2; ++dx) {
                const int xi = x0 + dx;
                if ((unsigned)xi >= (unsigned)GD) continue;
                const float w = (dx ? wx1 : wx0) * wyz;
                atomicAdd(&g_grid[base + xi], w);
            }
        }
    }
}

// ---------------------------------------------------------------------------
// Kernel 3: Huber-sum reduction over the diff grid (delta = 1).
// ---------------------------------------------------------------------------
__global__ void huber_kernel(float* __restrict__ out) {
    const float4* __restrict__ g4 = reinterpret_cast<const float4*>(g_grid);
    const int n4 = GRID_ELEMS / 4;

    float s = 0.f;
    for (int i = blockIdx.x * blockDim.x + threadIdx.x; i < n4;
         i += gridDim.x * blockDim.x) {
        float4 v = g4[i];
        float a;
        a = fabsf(v.x); s += (a <= 1.f) ? 0.5f * v.x * v.x : a - 0.5f;
        a = fabsf(v.y); s += (a <= 1.f) ? 0.5f * v.y * v.y : a - 0.5f;
        a = fabsf(v.z); s += (a <= 1.f) ? 0.5f * v.z * v.z : a - 0.5f;
        a = fabsf(v.w); s += (a <= 1.f) ? 0.5f * v.w * v.w : a - 0.5f;
    }

    // warp reduce
    #pragma unroll
    for (int o = 16; o; o >>= 1) s += __shfl_xor_sync(0xFFFFFFFFu, s, o);

    __shared__ float smem[32];
    const int lane = threadIdx.x & 31;
    const int warp = threadIdx.x >> 5;
    if (lane == 0) smem[warp] = s;
    __syncthreads();

    if (warp == 0) {
        const int nwarps = blockDim.x >> 5;
        s = (lane < nwarps) ? smem[lane] : 0.f;
        #pragma unroll
        for (int o = 16; o; o >>= 1) s += __shfl_xor_sync(0xFFFFFFFFu, s, o);
        if (lane == 0) atomicAdd(out, s);
    }
}

// ---------------------------------------------------------------------------
// Launch
// ---------------------------------------------------------------------------
extern "C" void kernel_launch(void* const* d_in, const int* in_sizes, int n_in,
                              void* d_out, int out_size) {
    const float* pred   = (const float*)d_in[0];  // registration_pred [1,N,3]
    const float* gt     = (const float*)d_in[1];  // registration_gt   [1,N,3]
    const float* coords = (const float*)d_in[2];  // coords            [1,N,3]
    float* out = (float*)d_out;

    const int N = in_sizes[0] / 3;

    // 1) zero grid + output
    {
        const int n4 = GRID_ELEMS / 4;
        const int threads = 256;
        zero_kernel<<<(n4 + threads - 1) / threads, threads>>>(out);
    }

    // 2) splat (2N splats: pred +1, gt -1)
    {
        const int threads = 256;
        const long long total = 2LL * N;
        splat_kernel<<<(int)((total + threads - 1) / threads), threads>>>(
            pred, gt, coords, N);
    }

    // 3) huber reduction
    {
        huber_kernel<<<1024, 256>>>(out);
    }
}

// round 2
// speedup vs baseline: 1.4169x; 1.4169x over previous
#include <cuda_runtime.h>
#include <cuda_bf16.h>

#define GD 128
#define GRID_ELEMS (GD * GD * GD)

// 8 MB scratch diff-grid (pred splat adds +w, gt splat adds -w).
// Zero-initialized at module load; huber_kernel re-zeroes it every call,
// so the zeroed-grid invariant holds across graph replays.
__device__ float g_grid[GRID_ELEMS];

__device__ __forceinline__ void red_add_f32(float* addr, float v) {
    asm volatile("red.global.add.f32 [%0], %1;" :: "l"(addr), "f"(v) : "memory");
}

__device__ __forceinline__ void red_add_v4(float* addr, float a, float b,
                                           float c, float d) {
    asm volatile("red.global.add.v4.f32 [%0], {%1, %2, %3, %4};"
                 :: "l"(addr), "f"(a), "f"(b), "f"(c), "f"(d) : "memory");
}

// ---------------------------------------------------------------------------
// Splat: thread i < N handles pred point i with +1, thread i >= N handles
// gt point (i-N) with -1. x-corner pairs are fused into one v4 red when both
// land in the same aligned 16B block (75% of points).
// ---------------------------------------------------------------------------
__global__ void splat_kernel(const float* __restrict__ pred,
                             const float* __restrict__ gt,
                             const float* __restrict__ coords,
                             int N, float* __restrict__ out) {
    int i = blockIdx.x * blockDim.x + threadIdx.x;
    if (i == 0) *out = 0.f;   // huber (next kernel) accumulates into out
    if (i >= 2 * N) return;

    const bool is_pred = (i < N);
    const int p = is_pred ? i : (i - N);
    const float* __restrict__ reg = is_pred ? pred : gt;
    const float sign = is_pred ? 1.0f : -1.0f;

    const float cx = coords[3 * p + 0] + reg[3 * p + 0];
    const float cy = coords[3 * p + 1] + reg[3 * p + 1];
    const float cz = coords[3 * p + 2] + reg[3 * p + 2];

    // pixel = ((c + 1) * 128 - 1) * 0.5 = 64*c + 63.5
    const float x = fmaf(cx, 64.0f, 63.5f);
    const float y = fmaf(cy, 64.0f, 63.5f);
    const float z = fmaf(cz, 64.0f, 63.5f);

    const float x0f = floorf(x), y0f = floorf(y), z0f = floorf(z);
    const float fx = x - x0f, fy = y - y0f, fz = z - z0f;
    const int x0 = (int)x0f, y0 = (int)y0f, z0 = (int)z0f;
    const int x1 = x0 + 1;

    const float wx0 = 1.0f - fx, wx1 = fx;
    const float wy0 = 1.0f - fy, wy1 = fy;
    const float wz0 = 1.0f - fz, wz1 = fz;

    const bool v0 = (unsigned)x0 < (unsigned)GD;
    const bool v1 = (unsigned)x1 < (unsigned)GD;
    const int lane = x0 & 3;
    const bool pair = v0 && v1 && (lane != 3);
    const int xb = x0 & ~3;   // aligned 16B block start (unused unless pair)

    #pragma unroll
    for (int dz = 0; dz < 2; ++dz) {
        const int zi = z0 + dz;
        if ((unsigned)zi >= (unsigned)GD) continue;
        const float wz = (dz ? wz1 : wz0) * sign;
        #pragma unroll
        for (int dy = 0; dy < 2; ++dy) {
            const int yi = y0 + dy;
            if ((unsigned)yi >= (unsigned)GD) continue;
            const float wyz = (dy ? wy1 : wy0) * wz;
            const int base = (zi * GD + yi) * GD;

            const float w0 = wx0 * wyz;
            const float w1 = wx1 * wyz;

            if (pair) {
                // place (w0, w1) at lanes (lane, lane+1) of the 16B block
                const float a = (lane == 0) ? w0 : 0.f;
                const float b = (lane == 0) ? w1 : ((lane == 1) ? w0 : 0.f);
                const float c = (lane == 1) ? w1 : ((lane == 2) ? w0 : 0.f);
                const float d = (lane == 2) ? w1 : 0.f;
                red_add_v4(&g_grid[base + xb], a, b, c, d);
            } else {
                if (v0) red_add_f32(&g_grid[base + x0], w0);
                if (v1) red_add_f32(&g_grid[base + x1], w1);
            }
        }
    }
}

// ---------------------------------------------------------------------------
// Huber-sum reduction over the diff grid (delta = 1) + grid reset to zero.
// ---------------------------------------------------------------------------
__global__ void huber_kernel(float* __restrict__ out) {
    float4* __restrict__ g4 = reinterpret_cast<float4*>(g_grid);
    const int n4 = GRID_ELEMS / 4;

    float s = 0.f;
    for (int i = blockIdx.x * blockDim.x + threadIdx.x; i < n4;
         i += gridDim.x * blockDim.x) {
        float4 v = g4[i];
        g4[i] = make_float4(0.f, 0.f, 0.f, 0.f);   // restore invariant
        float a;
        a = fabsf(v.x); s += (a <= 1.f) ? 0.5f * v.x * v.x : a - 0.5f;
        a = fabsf(v.y); s += (a <= 1.f) ? 0.5f * v.y * v.y : a - 0.5f;
        a = fabsf(v.z); s += (a <= 1.f) ? 0.5f * v.z * v.z : a - 0.5f;
        a = fabsf(v.w); s += (a <= 1.f) ? 0.5f * v.w * v.w : a - 0.5f;
    }

    #pragma unroll
    for (int o = 16; o; o >>= 1) s += __shfl_xor_sync(0xFFFFFFFFu, s, o);

    __shared__ float smem[32];
    const int lane = threadIdx.x & 31;
    const int warp = threadIdx.x >> 5;
    if (lane == 0) smem[warp] = s;
    __syncthreads();

    if (warp == 0) {
        const int nwarps = blockDim.x >> 5;
        s = (lane < nwarps) ? smem[lane] : 0.f;
        #pragma unroll
        for (int o = 16; o; o >>= 1) s += __shfl_xor_sync(0xFFFFFFFFu, s, o);
        if (lane == 0) atomicAdd(out, s);
    }
}

// ---------------------------------------------------------------------------
// Launch
// ---------------------------------------------------------------------------
extern "C" void kernel_launch(void* const* d_in, const int* in_sizes, int n_in,
                              void* d_out, int out_size) {
    const float* pred   = (const float*)d_in[0];  // registration_pred [1,N,3]
    const float* gt     = (const float*)d_in[1];  // registration_gt   [1,N,3]
    const float* coords = (const float*)d_in[2];  // coords            [1,N,3]
    float* out = (float*)d_out;

    const int N = in_sizes[0] / 3;

    {   // splat (2N splats: pred +1, gt -1); also zeroes *out
        const int threads = 256;
        const long long total = 2LL * N;
        splat_kernel<<<(int)((total + threads - 1) / threads), threads>>>(
            pred, gt, coords, N, out);
    }
    {   // huber reduction + grid reset
        huber_kernel<<<1184, 256>>>(out);
    }
}

// round 3
// speedup vs baseline: 2.5154x; 1.7753x over previous
#include <cuda_runtime.h>
#include <cuda_bf16.h>

#define GD 128
#define RX 66                      // padded (x/2) and (y/2) extent: [-2..129] -> 66 pairs
#define RZ 132                     // padded z layers: z0c in [0..131]
#define LAYER (RX * RX * 4)        // floats per z-layer per replica (17424)
#define REPSZ (RZ * LAYER)         // floats per replica (2,299,968)
#define TOTAL_FLOATS (4 * REPSZ)   // 9,199,872 floats = 36.8 MB

// 4 shifted replica grids. Zero at module load; zero_kernel restores the
// invariant after every huber pass, so graph replays always start from zero.
__device__ float g_rep[TOTAL_FLOATS];

__device__ __forceinline__ void red_add_v4(float* addr, float a, float b,
                                           float c, float d) {
    asm volatile("red.global.add.v4.f32 [%0], {%1, %2, %3, %4};"
                 :: "l"(addr), "f"(a), "f"(b), "f"(c), "f"(d) : "memory");
}

// ---------------------------------------------------------------------------
// Splat: one thread per point, splats pred (+1) and gt (-1).
// Each splat = 2 v4 reds (one per z-layer): the 2x2 xy corner face always
// occupies one aligned 16B block of the replica chosen by (x0&1, y0&1).
// Lane order within a block: lane = ly*2 + lx  (lx: x0->0, x1->1).
// ---------------------------------------------------------------------------
__device__ __forceinline__ void splat_one(float cx, float cy, float cz,
                                          float sign) {
    // pixel = ((c + 1) * 128 - 1) * 0.5 = 64*c + 63.5
    const float x = fmaf(cx, 64.0f, 63.5f);
    const float y = fmaf(cy, 64.0f, 63.5f);
    const float z = fmaf(cz, 64.0f, 63.5f);

    const float x0f = floorf(x), y0f = floorf(y), z0f = floorf(z);
    const float fx = x - x0f, fy = y - y0f, fz = z - z0f;
    int x0 = (int)x0f, y0 = (int)y0f, z0 = (int)z0f;
    // Clamp far-out points into the padded range; their corners stay OOB and
    // land in padding slots which the huber gather never reads.
    x0 = max(-2, min(128, x0));
    y0 = max(-2, min(128, y0));
    z0 = max(-2, min(128, z0));

    const float wx0 = 1.0f - fx, wx1 = fx;
    const float wy0 = 1.0f - fy, wy1 = fy;
    const float wz0 = (1.0f - fz) * sign, wz1 = fz * sign;

    const int sx = x0 & 1, sy = y0 & 1;
    const int col = (x0 + sx + 2) >> 1;          // 0..65
    const int row = (y0 + sy + 2) >> 1;          // 0..65
    const int rep = sy * 2 + sx;
    const int z0c = z0 + 2;                      // 0..130

    float* base = g_rep + (size_t)rep * REPSZ + (size_t)z0c * LAYER
                + ((row * RX + col) << 2);

    const float a = wx0 * wy0, b = wx1 * wy0, c = wx0 * wy1, d = wx1 * wy1;
    red_add_v4(base,         a * wz0, b * wz0, c * wz0, d * wz0);
    red_add_v4(base + LAYER, a * wz1, b * wz1, c * wz1, d * wz1);
}

__global__ void splat_kernel(const float* __restrict__ pred,
                             const float* __restrict__ gt,
                             const float* __restrict__ coords,
                             int N, float* __restrict__ out) {
    const int p = blockIdx.x * blockDim.x + threadIdx.x;
    if (p == 0) *out = 0.f;      // huber (next kernel) accumulates into out
    if (p >= N) return;

    const float cx = coords[3 * p + 0];
    const float cy = coords[3 * p + 1];
    const float cz = coords[3 * p + 2];

    splat_one(cx + pred[3 * p + 0], cy + pred[3 * p + 1],
              cz + pred[3 * p + 2],  1.0f);
    splat_one(cx + gt[3 * p + 0],   cy + gt[3 * p + 1],
              cz + gt[3 * p + 2],  -1.0f);
}

// ---------------------------------------------------------------------------
// Huber: for each real cell (x,y,z) gather its slot from all 4 replicas,
// sum, apply huber(delta=1), block-reduce, atomicAdd into out.
// 4 cells per thread (strided) -> 16 independent loads (MLP 16).
// ---------------------------------------------------------------------------
#define HUB_BLOCKS 2048
#define HUB_THREADS 256
#define HUB_STRIDE (HUB_BLOCKS * HUB_THREADS)   // 524,288; x4 = 2,097,152 cells

__global__ void huber_kernel(float* __restrict__ out) {
    const int t = blockIdx.x * HUB_THREADS + threadIdx.x;

    float s = 0.f;
    #pragma unroll
    for (int g = 0; g < 4; ++g) {
        const int cell = t + g * HUB_STRIDE;
        const int xx = cell & 127;
        const int yy = (cell >> 7) & 127;
        const int zz = cell >> 14;
        float v = 0.f;
        #pragma unroll
        for (int rep = 0; rep < 4; ++rep) {
            const int sx = rep & 1, sy = rep >> 1;
            const int col = (xx + sx + 2) >> 1;
            const int row = (yy + sy + 2) >> 1;
            const int lane = ((yy + sy) & 1) * 2 + ((xx + sx) & 1);
            v += g_rep[(size_t)rep * REPSZ + (size_t)(zz + 2) * LAYER
                       + ((row * RX + col) << 2) + lane];
        }
        const float a = fabsf(v);
        s += (a <= 1.f) ? 0.5f * v * v : a - 0.5f;
    }

    #pragma unroll
    for (int o = 16; o; o >>= 1) s += __shfl_xor_sync(0xFFFFFFFFu, s, o);

    __shared__ float smem[8];
    const int lane = threadIdx.x & 31;
    const int warp = threadIdx.x >> 5;
    if (lane == 0) smem[warp] = s;
    __syncthreads();

    if (warp == 0) {
        s = (lane < (HUB_THREADS >> 5)) ? smem[lane] : 0.f;
        #pragma unroll
        for (int o = 4; o; o >>= 1) s += __shfl_xor_sync(0xFFFFFFFFu, s, o);
        if (lane == 0) atomicAdd(out, s);
    }
}

// ---------------------------------------------------------------------------
// Zero the replica grids (runs after huber so replays start from zero).
// ---------------------------------------------------------------------------
__global__ void zero_kernel() {
    const int i = blockIdx.x * blockDim.x + threadIdx.x;
    const int n4 = TOTAL_FLOATS / 4;
    if (i < n4)
        reinterpret_cast<float4*>(g_rep)[i] = make_float4(0.f, 0.f, 0.f, 0.f);
}

// ---------------------------------------------------------------------------
// Launch: splat -> huber -> zero
// ---------------------------------------------------------------------------
extern "C" void kernel_launch(void* const* d_in, const int* in_sizes, int n_in,
                              void* d_out, int out_size) {
    const float* pred   = (const float*)d_in[0];  // registration_pred [1,N,3]
    const float* gt     = (const float*)d_in[1];  // registration_gt   [1,N,3]
    const float* coords = (const float*)d_in[2];  // coords            [1,N,3]
    float* out = (float*)d_out;

    const int N = in_sizes[0] / 3;

    {   // splat: one thread per point (pred +1, gt -1); also zeroes *out
        const int threads = 256;
        splat_kernel<<<(N + threads - 1) / threads, threads>>>(
            pred, gt, coords, N, out);
    }
    {   // huber gather + reduction
        huber_kernel<<<HUB_BLOCKS, HUB_THREADS>>>(out);
    }
    {   // reset replica grids for next replay
        const int n4 = TOTAL_FLOATS / 4;
        const int threads = 256;
        zero_kernel<<<(n4 + threads - 1) / threads, threads>>>();
    }
}

// round 4
// speedup vs baseline: 2.9282x; 1.1641x over previous
#include <cuda_runtime.h>
#include <cuda_bf16.h>

#define GD 128
#define RB 66                         // brick coords 0..65 cover x0 in [-2..128]
#define BRICKS (RB * RB * RB)         // 287,496 bricks per replica
#define REP_BRICKS BRICKS
#define TOTAL_BRICKS (8 * BRICKS)     // 8 parity replicas
// Each brick = 2x2x2 cells as bf16 = 16 bytes.
__device__ uint4 g_rep[TOTAL_BRICKS]; // 36.8 MB, zero-initialized at load;
                                      // zero_kernel restores invariant per call.

__device__ __forceinline__ unsigned pack_bf16x2(float lo, float hi) {
    unsigned u;
    asm("cvt.rn.bf16x2.f32 %0, %1, %2;" : "=r"(u) : "f"(hi), "f"(lo));
    return u;
}

__device__ __forceinline__ void red_add_v4_bf16x2(void* addr, unsigned a,
                                                  unsigned b, unsigned c,
                                                  unsigned d) {
    asm volatile("red.global.add.noftz.v4.bf16x2 [%0], {%1, %2, %3, %4};"
                 :: "l"(addr), "r"(a), "r"(b), "r"(c), "r"(d) : "memory");
}

// ---------------------------------------------------------------------------
// Splat: ONE red per splat. Replica chosen by (x0&1, y0&1, z0&1) so the full
// 2x2x2 corner cube occupies one aligned 16B brick.
// bf16 lane within brick: idx = lz*4 + ly*2 + lx  (lx in low half of bf16x2).
// ---------------------------------------------------------------------------
__device__ __forceinline__ void splat_one(float cx, float cy, float cz,
                                          float sign) {
    // pixel = ((c + 1) * 128 - 1) * 0.5 = 64*c + 63.5
    const float x = fmaf(cx, 64.0f, 63.5f);
    const float y = fmaf(cy, 64.0f, 63.5f);
    const float z = fmaf(cz, 64.0f, 63.5f);

    const float x0f = floorf(x), y0f = floorf(y), z0f = floorf(z);
    const float fx = x - x0f, fy = y - y0f, fz = z - z0f;
    int x0 = (int)x0f, y0 = (int)y0f, z0 = (int)z0f;
    // Far-out points clamp into padded range; their corners land in padding
    // slots that the huber gather never reads.
    x0 = max(-2, min(128, x0));
    y0 = max(-2, min(128, y0));
    z0 = max(-2, min(128, z0));

    const float wx0 = 1.0f - fx, wx1 = fx;
    const float wy0 = 1.0f - fy, wy1 = fy;
    const float wz0 = (1.0f - fz) * sign, wz1 = fz * sign;

    const int sx = x0 & 1, sy = y0 & 1, sz = z0 & 1;
    const int bx = (x0 + sx + 2) >> 1;           // 0..65
    const int by = (y0 + sy + 2) >> 1;
    const int bz = (z0 + sz + 2) >> 1;
    const int rep = (sz << 2) | (sy << 1) | sx;

    uint4* addr = g_rep + (size_t)rep * REP_BRICKS
                + ((size_t)bz * RB + by) * RB + bx;

    const float a00 = wx0 * wy0, a10 = wx1 * wy0;
    const float a01 = wx0 * wy1, a11 = wx1 * wy1;

    red_add_v4_bf16x2(addr,
        pack_bf16x2(a00 * wz0, a10 * wz0),   // (z0,y0): x0,x1
        pack_bf16x2(a01 * wz0, a11 * wz0),   // (z0,y1)
        pack_bf16x2(a00 * wz1, a10 * wz1),   // (z1,y0)
        pack_bf16x2(a01 * wz1, a11 * wz1));  // (z1,y1)
}

__global__ void splat_kernel(const float* __restrict__ pred,
                             const float* __restrict__ gt,
                             const float* __restrict__ coords,
                             int N, float* __restrict__ out) {
    const int p = blockIdx.x * blockDim.x + threadIdx.x;
    if (p == 0) *out = 0.f;      // huber (next kernel) accumulates into out
    if (p >= N) return;

    const float cx = coords[3 * p + 0];
    const float cy = coords[3 * p + 1];
    const float cz = coords[3 * p + 2];

    splat_one(cx + pred[3 * p + 0], cy + pred[3 * p + 1],
              cz + pred[3 * p + 2],  1.0f);
    splat_one(cx + gt[3 * p + 0],   cy + gt[3 * p + 1],
              cz + gt[3 * p + 2],  -1.0f);
}

// ---------------------------------------------------------------------------
// Huber: cell (x,y,z) value = sum over the 8 replicas of its unique slot.
// For replica shift s, the source cell is c - l where l = (c ^ s) & 1, and
// the slot is brick ((c - l + s + 2) >> 1), bf16 lane l per axis.
// 4 cells per thread -> 32 independent bf16 loads (MLP 32).
// ---------------------------------------------------------------------------
#define HUB_BLOCKS 2048
#define HUB_THREADS 256
#define HUB_STRIDE (HUB_BLOCKS * HUB_THREADS)   // 524,288; x4 = 2,097,152 cells

__global__ void huber_kernel(float* __restrict__ out) {
    const __nv_bfloat16* __restrict__ gb =
        reinterpret_cast<const __nv_bfloat16*>(g_rep);
    const int t = blockIdx.x * HUB_THREADS + threadIdx.x;

    float s = 0.f;
    #pragma unroll
    for (int g = 0; g < 4; ++g) {
        const int cell = t + g * HUB_STRIDE;
        const int xx = cell & 127;
        const int yy = (cell >> 7) & 127;
        const int zz = cell >> 14;
        float v = 0.f;
        #pragma unroll
        for (int rep = 0; rep < 8; ++rep) {
            const int sx = rep & 1, sy = (rep >> 1) & 1, sz = rep >> 2;
            const int lx = (xx ^ sx) & 1;
            const int ly = (yy ^ sy) & 1;
            const int lz = (zz ^ sz) & 1;
            const int bx = (xx - lx + sx + 2) >> 1;
            const int by = (yy - ly + sy + 2) >> 1;
            const int bz = (zz - lz + sz + 2) >> 1;
            const size_t brick = (size_t)rep * REP_BRICKS
                               + ((size_t)bz * RB + by) * RB + bx;
            v += __bfloat162float(gb[brick * 8 + (lz << 2) + (ly << 1) + lx]);
        }
        const float a = fabsf(v);
        s += (a <= 1.f) ? 0.5f * v * v : a - 0.5f;
    }

    #pragma unroll
    for (int o = 16; o; o >>= 1) s += __shfl_xor_sync(0xFFFFFFFFu, s, o);

    __shared__ float smem[8];
    const int lane = threadIdx.x & 31;
    const int warp = threadIdx.x >> 5;
    if (lane == 0) smem[warp] = s;
    __syncthreads();

    if (warp == 0) {
        s = (lane < (HUB_THREADS >> 5)) ? smem[lane] : 0.f;
        #pragma unroll
        for (int o = 4; o; o >>= 1) s += __shfl_xor_sync(0xFFFFFFFFu, s, o);
        if (lane == 0) atomicAdd(out, s);
    }
}

// ---------------------------------------------------------------------------
// Zero the replica bricks (runs after huber so replays start from zero).
// ---------------------------------------------------------------------------
__global__ void zero_kernel() {
    const int i = blockIdx.x * blockDim.x + threadIdx.x;
    if (i < TOTAL_BRICKS)
        g_rep[i] = make_uint4(0u, 0u, 0u, 0u);
}

// ---------------------------------------------------------------------------
// Launch: splat -> huber -> zero
// ---------------------------------------------------------------------------
extern "C" void kernel_launch(void* const* d_in, const int* in_sizes, int n_in,
                              void* d_out, int out_size) {
    const float* pred   = (const float*)d_in[0];  // registration_pred [1,N,3]
    const float* gt     = (const float*)d_in[1];  // registration_gt   [1,N,3]
    const float* coords = (const float*)d_in[2];  // coords            [1,N,3]
    float* out = (float*)d_out;

    const int N = in_sizes[0] / 3;

    {   // splat: one thread per point (pred +1, gt -1); also zeroes *out
        const int threads = 256;
        splat_kernel<<<(N + threads - 1) / threads, threads>>>(
            pred, gt, coords, N, out);
    }
    {   // huber gather + reduction
        huber_kernel<<<HUB_BLOCKS, HUB_THREADS>>>(out);
    }
    {   // reset replica bricks for next replay
        const int threads = 256;
        zero_kernel<<<(TOTAL_BRICKS + threads - 1) / threads, threads>>>();
    }
}